// round 2
// baseline (speedup 1.0000x reference)
#include <cuda_runtime.h>
#include <cuda_bf16.h>
#include <cstdint>

#define NTOK   4096
#define DMODEL 1024
#define DFF    4096
#define NEXP   16
#define NPAIR  (NTOK*2)
#define WNB    64

// ---------------- scratch (device globals; no cudaMalloc allowed) ----------------
__device__ float g_ws_part[32*WNB];
__device__ float g_wscale[32];
__device__ float g_paux[NEXP];
__device__ int   g_cnt[NEXP];
__device__ int   g_off[NEXP+1];
__device__ float g_probs[(size_t)NEXP*NTOK];
__device__ int   g_fcnt[NEXP];
__device__ float g_rstd[NTOK];
__device__ int   g_pair_e[NPAIR];
__device__ int   g_pair_pos[NPAIR];
__device__ float g_pair_w[NPAIR];
__device__ int   g_pair_slot[NPAIR];
__device__ int   g_slot_tok[NPAIR];
__device__ float g_slot_cw[NPAIR];
__device__ float g_ascale1[NPAIR];
__device__ float g_ascale2[NPAIR];
__device__ int8_t g_A1q[(size_t)NPAIR*DMODEL];        // 8 MB
__device__ int8_t g_A2q[(size_t)NPAIR*DFF];           // 32 MB
__device__ int8_t g_W1q[(size_t)NEXP*DFF*DMODEL];     // 64 MB
__device__ int8_t g_W2q[(size_t)NEXP*DMODEL*DFF];     // 64 MB
__device__ float  g_H[(size_t)NPAIR*DFF];             // 128 MB (H, then reused as O rows)

// ---------------- helpers ----------------
__device__ __forceinline__ float warpSum(float v){
#pragma unroll
  for (int o=16;o>0;o>>=1) v += __shfl_xor_sync(0xffffffffu, v, o);
  return v;
}
__device__ __forceinline__ float warpMax(float v){
#pragma unroll
  for (int o=16;o>0;o>>=1) v = fmaxf(v, __shfl_xor_sync(0xffffffffu, v, o));
  return v;
}
__device__ __forceinline__ float gelu_tanh(float x){
  float x3 = x*x*x;
  return 0.5f*x*(1.f + tanhf(0.7978845608028654f*(x + 0.044715f*x3)));
}

// ---------------- K0: reset counters ----------------
__global__ void k0_init(){
  int i = threadIdx.x;
  if (i < NEXP){ g_cnt[i]=0; g_fcnt[i]=0; }
}

// ---------------- K1: per-expert-matrix sum(|w|) partials ----------------
__global__ void k1_wsum(const float* __restrict__ w1, const float* __restrict__ w2){
  int m = blockIdx.y;  // 0..15 -> w1[e], 16..31 -> w2[e]
  const float* base = (m<16) ? (w1 + (size_t)m*DFF*DMODEL)
                             : (w2 + (size_t)(m-16)*(size_t)DMODEL*DFF);
  const int chunk = (DFF*DMODEL)/WNB;  // 65536 floats
  const float4* p = (const float4*)(base + (size_t)blockIdx.x*chunk);
  float s = 0.f;
  for (int i=threadIdx.x; i<chunk/4; i+=blockDim.x){
    float4 v = p[i];
    s += fabsf(v.x)+fabsf(v.y)+fabsf(v.z)+fabsf(v.w);
  }
  s = warpSum(s);
  __shared__ float sm[8];
  int lane=threadIdx.x&31, wid=threadIdx.x>>5;
  if (lane==0) sm[wid]=s;
  __syncthreads();
  if (threadIdx.x==0){
    float tot=0.f;
#pragma unroll
    for (int i=0;i<8;i++) tot+=sm[i];
    g_ws_part[m*WNB + blockIdx.x] = tot;
  }
}

// ---------------- K2: router (logits, softmax, top-2, rstd) ----------------
__global__ void k2_router(const float* __restrict__ x, const float* __restrict__ rw){
  int t = blockIdx.x;
  const float4* xr = (const float4*)(x + (size_t)t*DMODEL);
  int tid = threadIdx.x;   // 128 threads
  float lg[16];
#pragma unroll
  for (int e=0;e<16;e++) lg[e]=0.f;
  float ss = 0.f;
#pragma unroll
  for (int j=0;j<2;j++){
    float4 xv = xr[tid*2+j];
    ss += xv.x*xv.x + xv.y*xv.y + xv.z*xv.z + xv.w*xv.w;
#pragma unroll
    for (int e=0;e<16;e++){
      float4 rv = ((const float4*)(rw + (size_t)e*DMODEL))[tid*2+j];
      lg[e] += xv.x*rv.x + xv.y*rv.y + xv.z*rv.z + xv.w*rv.w;
    }
  }
#pragma unroll
  for (int e=0;e<16;e++) lg[e] = warpSum(lg[e]);
  ss = warpSum(ss);

  __shared__ float sh[4][17];
  int lane=tid&31, wid=tid>>5;
  if (lane==0){
#pragma unroll
    for (int e=0;e<16;e++) sh[wid][e]=lg[e];
    sh[wid][16]=ss;
  }
  __syncthreads();
  __shared__ float fin[17];
  if (tid<17) fin[tid] = sh[0][tid]+sh[1][tid]+sh[2][tid]+sh[3][tid];
  __syncthreads();
  __shared__ float spr[16];
  if (tid==0){
    g_rstd[t] = rsqrtf(fin[16]*(1.f/DMODEL) + 1e-6f);
    float mx = fin[0];
#pragma unroll
    for (int e=1;e<16;e++) mx = fmaxf(mx, fin[e]);
    float p[16]; float s=0.f;
#pragma unroll
    for (int e=0;e<16;e++){ p[e]=expf(fin[e]-mx); s+=p[e]; }
    float inv = 1.f/s;
#pragma unroll
    for (int e=0;e<16;e++){ p[e]*=inv; spr[e]=p[e]; }
    int b1=0;
#pragma unroll
    for (int e=1;e<16;e++) if (fin[e]>fin[b1]) b1=e;
    int b2 = (b1==0)?1:0;
#pragma unroll
    for (int e=0;e<16;e++) if (e!=b1 && fin[e]>fin[b2]) b2=e;
    float ps = p[b1]+p[b2]+1e-8f;
    int pos1 = atomicAdd(&g_cnt[b1],1);
    int pos2 = atomicAdd(&g_cnt[b2],1);
    g_pair_e[2*t]=b1;   g_pair_pos[2*t]=pos1;   g_pair_w[2*t]=p[b1]/ps;
    g_pair_e[2*t+1]=b2; g_pair_pos[2*t+1]=pos2; g_pair_w[2*t+1]=p[b2]/ps;
    atomicAdd(&g_fcnt[b1],1);
    atomicAdd(&g_fcnt[b2],1);
  }
  __syncthreads();
  if (tid<16) g_probs[(size_t)tid*NTOK + t] = spr[tid];
}

// ---------------- K3a: reduce probs per expert (parallel) ----------------
__global__ void k3a_paux(){
  int e = blockIdx.x;
  int tid = threadIdx.x;  // 256
  const float* pr = g_probs + (size_t)e*NTOK;
  float s = 0.f;
  for (int i=tid;i<NTOK;i+=256) s += pr[i];
  s = warpSum(s);
  __shared__ float sm[8];
  int lane=tid&31, wid=tid>>5;
  if (lane==0) sm[wid]=s;
  __syncthreads();
  if (tid==0){
    float tot=0.f;
#pragma unroll
    for (int i=0;i<8;i++) tot+=sm[i];
    g_paux[e]=tot;
  }
}

// ---------------- K3b: wscales, offsets, aux loss ----------------
__global__ void k3b_finalize(float* __restrict__ out, long long out_size){
  int tid = threadIdx.x;  // 256
  if (tid < 32){
    float s = 0.f;
    for (int i=0;i<WNB;i++) s += g_ws_part[tid*WNB+i];
    float mean = s * (1.f/((float)DFF*(float)DMODEL));
    g_wscale[tid] = 1.f/fmaxf(mean, 1e-5f);
  }
  if (tid==0){
    int o=0;
#pragma unroll
    for (int e=0;e<NEXP;e++){ g_off[e]=o; o+=g_cnt[e]; }
    g_off[NEXP]=o;
    if (out_size > (long long)NTOK*DMODEL){
      float aux=0.f;
#pragma unroll
      for (int e=0;e<16;e++){
        float pm = g_paux[e] * (1.f/NTOK);
        aux += ((float)g_fcnt[e]/(float)(NTOK*2)) * pm;
      }
      out[(size_t)NTOK*DMODEL] = (float)NEXP * aux;
    }
  }
}

// ---------------- K5: pre-quantize W to ternary int8 ----------------
__global__ void k5_quantw(const float* __restrict__ w1, const float* __restrict__ w2){
  int m = blockIdx.y;
  const float* src = (m<16) ? (w1 + (size_t)m*DFF*DMODEL)
                            : (w2 + (size_t)(m-16)*(size_t)DMODEL*DFF);
  int8_t* dst = (m<16) ? (g_W1q + (size_t)m*DFF*DMODEL)
                       : (g_W2q + (size_t)(m-16)*(size_t)DMODEL*DFF);
  float ws = g_wscale[m];
  int i = blockIdx.x*blockDim.x + threadIdx.x;   // each handles 16 elements
  const float4* s4 = (const float4*)src + (size_t)i*4;
  int8_t o[16];
#pragma unroll
  for (int j=0;j<4;j++){
    float4 v = s4[j];
    int q0 = max(-1, min(1, __float2int_rn(v.x*ws)));
    int q1 = max(-1, min(1, __float2int_rn(v.y*ws)));
    int q2 = max(-1, min(1, __float2int_rn(v.z*ws)));
    int q3 = max(-1, min(1, __float2int_rn(v.w*ws)));
    o[j*4+0]=(int8_t)q0; o[j*4+1]=(int8_t)q1; o[j*4+2]=(int8_t)q2; o[j*4+3]=(int8_t)q3;
  }
  ((int4*)dst)[i] = *(int4*)o;
}

// ---------------- K4: layer-1 rmsnorm + act_quant to int8 (sorted slots) --------
__global__ void k4_quant1(const float* __restrict__ x, const float* __restrict__ g1){
  int p = blockIdx.x;
  int t = p>>1;
  int e = g_pair_e[p];
  int slot = g_off[e] + g_pair_pos[p];
  float r = g_rstd[t];
  const float4* xr = (const float4*)(x  + (size_t)t*DMODEL);
  const float4* gr = (const float4*)(g1 + (size_t)e*DMODEL);
  int tid = threadIdx.x;  // 128
  float v[8]; float am=0.f;
#pragma unroll
  for (int j=0;j<2;j++){
    float4 xv=xr[tid*2+j]; float4 gv=gr[tid*2+j];
    v[j*4+0]=xv.x*gv.x*r; v[j*4+1]=xv.y*gv.y*r;
    v[j*4+2]=xv.z*gv.z*r; v[j*4+3]=xv.w*gv.w*r;
#pragma unroll
    for (int k=0;k<4;k++) am = fmaxf(am, fabsf(v[j*4+k]));
  }
  am = warpMax(am);
  __shared__ float sm[4]; __shared__ float as_s;
  int lane=tid&31, wid=tid>>5;
  if (lane==0) sm[wid]=am;
  __syncthreads();
  if (tid==0){
    float m = fmaxf(fmaxf(sm[0],sm[1]), fmaxf(sm[2],sm[3]));
    as_s = 127.f/fmaxf(m, 1e-5f);
    g_ascale1[slot]=as_s;
    g_slot_tok[slot]=t;
    g_slot_cw[slot]=g_pair_w[p];
    g_pair_slot[p]=slot;
  }
  __syncthreads();
  float as = as_s;
  int8_t o[8];
#pragma unroll
  for (int j=0;j<8;j++){
    int q = max(-128, min(127, __float2int_rn(v[j]*as)));
    o[j] = (int8_t)q;
  }
  ((int2*)(g_A1q + (size_t)slot*DMODEL))[tid] = *(int2*)o;
}

// ---------------- K6: layer-2 rmsnorm + act_quant to int8 ----------------
__global__ void k6_quant2(const float* __restrict__ g2){
  int slot = blockIdx.x;
  int e = 0;
#pragma unroll
  for (int i=1;i<NEXP;i++) if (slot >= g_off[i]) e = i;
  const float4* h4 = (const float4*)(g_H + (size_t)slot*DFF);
  const float4* g4 = (const float4*)(g2  + (size_t)e*DFF);
  int tid = threadIdx.x;  // 256
  float v[16]; float ss=0.f;
#pragma unroll
  for (int j=0;j<4;j++){
    float4 a = h4[tid*4+j];
    v[j*4+0]=a.x; v[j*4+1]=a.y; v[j*4+2]=a.z; v[j*4+3]=a.w;
    ss += a.x*a.x + a.y*a.y + a.z*a.z + a.w*a.w;
  }
  ss = warpSum(ss);
  __shared__ float sred[8];
  __shared__ float rstd_s, as_s;
  int lane=tid&31, wid=tid>>5;
  if (lane==0) sred[wid]=ss;
  __syncthreads();
  if (tid==0){
    float s=0.f;
#pragma unroll
    for (int i=0;i<8;i++) s+=sred[i];
    rstd_s = rsqrtf(s*(1.f/DFF) + 1e-6f);
  }
  __syncthreads();
  float r2 = rstd_s;
  float am = 0.f;
#pragma unroll
  for (int j=0;j<4;j++){
    float4 gg = g4[tid*4+j];
    v[j*4+0]*=gg.x*r2; v[j*4+1]*=gg.y*r2; v[j*4+2]*=gg.z*r2; v[j*4+3]*=gg.w*r2;
#pragma unroll
    for (int k=0;k<4;k++) am = fmaxf(am, fabsf(v[j*4+k]));
  }
  am = warpMax(am);
  if (lane==0) sred[wid]=am;
  __syncthreads();
  if (tid==0){
    float m=0.f;
#pragma unroll
    for (int i=0;i<8;i++) m=fmaxf(m,sred[i]);
    as_s = 127.f/fmaxf(m,1e-5f);
    g_ascale2[slot]=as_s;
  }
  __syncthreads();
  float as = as_s;
  int8_t o[16];
#pragma unroll
  for (int j=0;j<16;j++){
    int q = max(-128, min(127, __float2int_rn(v[j]*as)));
    o[j] = (int8_t)q;
  }
  ((int4*)(g_A2q + (size_t)slot*DFF))[tid] = *(int4*)o;
}

// ---------------- int8 GEMM: mma.m16n8k32.s8, cp.async pipeline, ldmatrix -------
template<int KDIM, int NTOT, bool L1>
__global__ void __launch_bounds__(256) gemm_i8(float* __restrict__ outp)
{
  constexpr int NST = 4;
  constexpr int KT  = KDIM/32;
  __shared__ int8_t As[NST][128][48];
  __shared__ int8_t Bs[NST][128][48];

  const int e  = blockIdx.z;
  const int mt = blockIdx.x;
  const int nt = blockIdx.y;
  const int cnt = g_cnt[e];
  if (mt*128 >= cnt) return;
  const int off = g_off[e];
  const int8_t* __restrict__ A = (L1 ? g_A1q : g_A2q) + (size_t)off*KDIM;
  const int8_t* __restrict__ W = (L1 ? g_W1q : g_W2q)
                                 + ((size_t)e*NTOT + (size_t)nt*128)*(size_t)KDIM;
  const float ws = g_wscale[L1 ? e : 16+e];

  const int tid = threadIdx.x;
  const int lane = tid & 31, warp = tid >> 5;
  const int wm = warp >> 2, wn = warp & 3;   // 2 x 4 warp grid (64x32 per warp)
  const int gq = lane >> 2, tq = lane & 3;

  const int lrow  = tid >> 1;
  const int lhalf = tid & 1;
  const bool arow_ok = (mt*128 + lrow) < cnt;
  const int8_t* Ag = A + (size_t)(mt*128 + lrow)*KDIM + lhalf*16;
  const int8_t* Wg = W + (size_t)lrow*KDIM + lhalf*16;

  int acc[4][4][4];
#pragma unroll
  for (int a=0;a<4;a++)
#pragma unroll
    for (int b=0;b<4;b++)
#pragma unroll
      for (int c=0;c<4;c++) acc[a][b][c]=0;

  auto load_stage = [&](int st, int kt){
    uint32_t da = (uint32_t)__cvta_generic_to_shared(&As[st][lrow][lhalf*16]);
    uint32_t db = (uint32_t)__cvta_generic_to_shared(&Bs[st][lrow][lhalf*16]);
    int pa = arow_ok ? 16 : 0;
    asm volatile("cp.async.cg.shared.global [%0],[%1],16,%2;\n"
                 ::"r"(da),"l"(Ag + (size_t)kt*32),"r"(pa));
    asm volatile("cp.async.cg.shared.global [%0],[%1],16;\n"
                 ::"r"(db),"l"(Wg + (size_t)kt*32));
  };

#pragma unroll
  for (int s=0;s<NST-1;s++){
    load_stage(s, s);
    asm volatile("cp.async.commit_group;\n");
  }

  for (int kt=0; kt<KT; kt++){
    asm volatile("cp.async.wait_group %0;\n"::"n"(NST-2));
    __syncthreads();
    if (kt+NST-1 < KT) load_stage((kt+NST-1)%NST, kt+NST-1);
    asm volatile("cp.async.commit_group;\n");

    const int st = kt % NST;
    uint32_t af[4][4], bfr[4][2];
#pragma unroll
    for (int mi=0;mi<4;mi++){
      int r = wm*64 + mi*16 + (lane & 15);
      uint32_t addr = (uint32_t)__cvta_generic_to_shared(&As[st][r][(lane>>4)*16]);
      asm volatile("ldmatrix.sync.aligned.m8n8.x4.shared.b16 {%0,%1,%2,%3},[%4];\n"
                   : "=r"(af[mi][0]),"=r"(af[mi][1]),"=r"(af[mi][2]),"=r"(af[mi][3])
                   : "r"(addr));
    }
#pragma unroll
    for (int ni=0;ni<4;ni++){
      int r = wn*32 + ni*8 + (lane & 7);
      uint32_t addr = (uint32_t)__cvta_generic_to_shared(&Bs[st][r][((lane>>3)&1)*16]);
      asm volatile("ldmatrix.sync.aligned.m8n8.x2.shared.b16 {%0,%1},[%2];\n"
                   : "=r"(bfr[ni][0]),"=r"(bfr[ni][1])
                   : "r"(addr));
    }
#pragma unroll
    for (int mi=0;mi<4;mi++)
#pragma unroll
      for (int ni=0;ni<4;ni++)
        asm volatile(
          "mma.sync.aligned.m16n8k32.row.col.s32.s8.s8.s32 "
          "{%0,%1,%2,%3}, {%4,%5,%6,%7}, {%8,%9}, {%0,%1,%2,%3};\n"
          : "+r"(acc[mi][ni][0]), "+r"(acc[mi][ni][1]),
            "+r"(acc[mi][ni][2]), "+r"(acc[mi][ni][3])
          : "r"(af[mi][0]), "r"(af[mi][1]), "r"(af[mi][2]), "r"(af[mi][3]),
            "r"(bfr[ni][0]), "r"(bfr[ni][1]));
  }

  // ---------------- epilogue ----------------
  const int base_m = mt*128 + wm*64;
  const int base_n = nt*128 + wn*32;
#pragma unroll
  for (int mi=0;mi<4;mi++){
#pragma unroll
    for (int h=0;h<2;h++){
      int r = base_m + mi*16 + gq + h*8;
      if (r < cnt){
        int slot = off + r;
        if (L1){
          float dq = 1.f/(g_ascale1[slot]*ws);
          float* Hr = g_H + (size_t)slot*DFF;
#pragma unroll
          for (int ni=0;ni<4;ni++){
            int c = base_n + ni*8 + tq*2;
            float2 v;
            v.x = gelu_tanh((float)acc[mi][ni][h*2+0]*dq);
            v.y = gelu_tanh((float)acc[mi][ni][h*2+1]*dq);
            *(float2*)&Hr[c] = v;
          }
        } else {
          float coef = g_slot_cw[slot]/(g_ascale2[slot]*ws);
          float* Or = g_H + (size_t)slot*DMODEL;   // reuse g_H as per-slot O rows
#pragma unroll
          for (int ni=0;ni<4;ni++){
            int c = base_n + ni*8 + tq*2;
            float2 v;
            v.x = (float)acc[mi][ni][h*2+0]*coef;
            v.y = (float)acc[mi][ni][h*2+1]*coef;
            *(float2*)&Or[c] = v;
          }
        }
      }
    }
  }
}

// ---------------- K7: combine 2 expert rows per token ----------------
__global__ void k7_combine(float* __restrict__ out){
  int t = blockIdx.x;
  int tid = threadIdx.x;  // 256
  int s0 = g_pair_slot[2*t];
  int s1 = g_pair_slot[2*t+1];
  const float4* a = (const float4*)(g_H + (size_t)s0*DMODEL);
  const float4* b = (const float4*)(g_H + (size_t)s1*DMODEL);
  float4 va = a[tid], vb = b[tid];
  float4 r; r.x=va.x+vb.x; r.y=va.y+vb.y; r.z=va.z+vb.z; r.w=va.w+vb.w;
  ((float4*)(out + (size_t)t*DMODEL))[tid] = r;
}

// ---------------- launch ----------------
extern "C" void kernel_launch(void* const* d_in, const int* in_sizes, int n_in,
                              void* d_out, int out_size){
  const float* x  = (const float*)d_in[0];
  const float* rw = (const float*)d_in[1];
  const float* w1 = (const float*)d_in[2];
  const float* g1 = (const float*)d_in[3];
  const float* w2 = (const float*)d_in[4];
  const float* g2 = (const float*)d_in[5];
  float* out = (float*)d_out;

  k0_init<<<1,32>>>();
  k1_wsum<<<dim3(WNB,32),256>>>(w1, w2);
  k2_router<<<NTOK,128>>>(x, rw);
  k3a_paux<<<NEXP,256>>>();
  k3b_finalize<<<1,256>>>(out, (long long)out_size);
  k5_quantw<<<dim3(1024,32),256>>>(w1, w2);
  k4_quant1<<<NPAIR,128>>>(x, g1);
  gemm_i8<DMODEL,DFF,true><<<dim3(32,DFF/128,NEXP),256>>>(nullptr);
  k6_quant2<<<NPAIR,256>>>(g2);
  gemm_i8<DFF,DMODEL,false><<<dim3(32,DMODEL/128,NEXP),256>>>(out);
  k7_combine<<<NTOK,256>>>(out);
}

// round 14
// speedup vs baseline: 1.0199x; 1.0199x over previous
#include <cuda_runtime.h>
#include <cuda_bf16.h>
#include <cstdint>

#define NTOK   4096
#define DMODEL 1024
#define DFF    4096
#define NEXP   16
#define NPAIR  (NTOK*2)
#define ELEM_PER_MAT 4194304  // DFF*DMODEL

// ---------------- scratch (device globals) ----------------
__device__ float g_ws_part[32*64];
__device__ float g_paux[NEXP];
__device__ int   g_cnt[NEXP];      // zero on entry; re-zeroed by k7 block 0 each run
__device__ int   g_fcnt[NEXP];
__device__ int   g_off[NEXP+1];
__device__ float g_probs[(size_t)NEXP*NTOK];
__device__ float g_rstd[NTOK];
__device__ int   g_pair_e[NPAIR];
__device__ int   g_pair_pos[NPAIR];
__device__ float g_pair_w[NPAIR];
__device__ int   g_pair_slot[NPAIR];
__device__ float g_slot_cw[NPAIR];
__device__ float g_ascale1[NPAIR];
__device__ float g_ascale2[NPAIR];
__device__ int8_t g_A1q[(size_t)NPAIR*DMODEL];        // 8 MB
__device__ int8_t g_A2q[(size_t)NPAIR*DFF];           // 32 MB
__device__ int8_t g_W1q[(size_t)NEXP*ELEM_PER_MAT];   // 64 MB
__device__ int8_t g_W2q[(size_t)NEXP*ELEM_PER_MAT];   // 64 MB
__device__ float  g_H[(size_t)NPAIR*DFF];             // 128 MB (H, then reused as O rows)

// ---------------- helpers ----------------
__device__ __forceinline__ float warpSum(float v){
#pragma unroll
  for (int o=16;o>0;o>>=1) v += __shfl_xor_sync(0xffffffffu, v, o);
  return v;
}
__device__ __forceinline__ float warpMax(float v){
#pragma unroll
  for (int o=16;o>0;o>>=1) v = fmaxf(v, __shfl_xor_sync(0xffffffffu, v, o));
  return v;
}
__device__ __forceinline__ float gelu_tanh(float x){
  float x3 = x*x*x;
  return 0.5f*x*(1.f + tanhf(0.7978845608028654f*(x + 0.044715f*x3)));
}
__device__ __forceinline__ uint32_t smem_u32(const void* p){
  uint32_t a;
  asm("{ .reg .u64 t; cvta.to.shared.u64 t, %1; cvt.u32.u64 %0, t; }" : "=r"(a) : "l"(p));
  return a;
}
__device__ __forceinline__ uint32_t pack4i8(int a, int b, int c, int d){
  return (uint32_t)(a&255) | ((uint32_t)(b&255)<<8) | ((uint32_t)(c&255)<<16) | ((uint32_t)(d&255)<<24);
}
__device__ __forceinline__ float wscale_from_parts(int m){
  float s = 0.f;
#pragma unroll
  for (int i=0;i<64;i++) s += g_ws_part[m*64+i];
  return 1.f/fmaxf(s*(1.f/(float)ELEM_PER_MAT), 1e-5f);
}

// ---------------- kA: per-matrix sum(|w|) partials (deterministic) ----------------
__global__ void kA_wsum(const float* __restrict__ w1, const float* __restrict__ w2){
  int m = blockIdx.y;
  const float* base = (m<16) ? (w1 + (size_t)m*ELEM_PER_MAT)
                             : (w2 + (size_t)(m-16)*ELEM_PER_MAT);
  const int chunk = ELEM_PER_MAT/64;
  const float4* p = (const float4*)(base + (size_t)blockIdx.x*chunk);
  float s = 0.f;
  for (int i=threadIdx.x; i<chunk/4; i+=blockDim.x){
    float4 v = p[i];
    s += fabsf(v.x)+fabsf(v.y)+fabsf(v.z)+fabsf(v.w);
  }
  s = warpSum(s);
  __shared__ float sm[8];
  int lane=threadIdx.x&31, wid=threadIdx.x>>5;
  if (lane==0) sm[wid]=s;
  __syncthreads();
  if (threadIdx.x==0){
    float tot=0.f;
#pragma unroll
    for (int i=0;i<8;i++) tot+=sm[i];
    g_ws_part[m*64 + blockIdx.x] = tot;
  }
}

// ---------------- k2: router ----------------
__global__ void k2_router(const float* __restrict__ x, const float* __restrict__ rw){
  int t = blockIdx.x;
  const float4* xr = (const float4*)(x + (size_t)t*DMODEL);
  int tid = threadIdx.x;   // 128
  float lg[16];
#pragma unroll
  for (int e=0;e<16;e++) lg[e]=0.f;
  float ss = 0.f;
#pragma unroll
  for (int j=0;j<2;j++){
    float4 xv = xr[tid*2+j];
    ss += xv.x*xv.x + xv.y*xv.y + xv.z*xv.z + xv.w*xv.w;
#pragma unroll
    for (int e=0;e<16;e++){
      float4 rv = ((const float4*)(rw + (size_t)e*DMODEL))[tid*2+j];
      lg[e] += xv.x*rv.x + xv.y*rv.y + xv.z*rv.z + xv.w*rv.w;
    }
  }
#pragma unroll
  for (int e=0;e<16;e++) lg[e] = warpSum(lg[e]);
  ss = warpSum(ss);

  __shared__ float sh[4][17];
  int lane=tid&31, wid=tid>>5;
  if (lane==0){
#pragma unroll
    for (int e=0;e<16;e++) sh[wid][e]=lg[e];
    sh[wid][16]=ss;
  }
  __syncthreads();
  __shared__ float fin[17];
  if (tid<17) fin[tid] = sh[0][tid]+sh[1][tid]+sh[2][tid]+sh[3][tid];
  __syncthreads();
  __shared__ float spr[16];
  if (tid==0){
    g_rstd[t] = rsqrtf(fin[16]*(1.f/DMODEL) + 1e-6f);
    float mx = fin[0];
#pragma unroll
    for (int e=1;e<16;e++) mx = fmaxf(mx, fin[e]);
    float p[16]; float s=0.f;
#pragma unroll
    for (int e=0;e<16;e++){ p[e]=expf(fin[e]-mx); s+=p[e]; }
    float inv = 1.f/s;
#pragma unroll
    for (int e=0;e<16;e++){ p[e]*=inv; spr[e]=p[e]; }
    int b1=0;
#pragma unroll
    for (int e=1;e<16;e++) if (fin[e]>fin[b1]) b1=e;
    int b2 = (b1==0)?1:0;
#pragma unroll
    for (int e=0;e<16;e++) if (e!=b1 && fin[e]>fin[b2]) b2=e;
    float ps = p[b1]+p[b2]+1e-8f;
    int pos1 = atomicAdd(&g_cnt[b1],1);
    int pos2 = atomicAdd(&g_cnt[b2],1);
    g_pair_e[2*t]=b1;   g_pair_pos[2*t]=pos1;   g_pair_w[2*t]=p[b1]/ps;
    g_pair_e[2*t+1]=b2; g_pair_pos[2*t+1]=pos2; g_pair_w[2*t+1]=p[b2]/ps;
    atomicAdd(&g_fcnt[b1],1);
    atomicAdd(&g_fcnt[b2],1);
  }
  __syncthreads();
  if (tid<16) g_probs[(size_t)tid*NTOK + t] = spr[tid];
}

// ---------------- k45: fused activation-quant (A1 int8) + weight-quant (int8) ----
__global__ void k45(const float* __restrict__ x, const float* __restrict__ g1,
                    const float* __restrict__ w1, const float* __restrict__ w2){
  int tid = threadIdx.x;  // 256
  if (blockIdx.x < NPAIR){
    // ----- activation path -----
    int p = blockIdx.x;
    int t = p>>1;
    int e = g_pair_e[p];
    __shared__ int off_s; __shared__ float red[8]; __shared__ float as_s; __shared__ int slot_s;
    if (tid==0){
      int o=0;
#pragma unroll
      for (int i=0;i<16;i++){ if (i<e) o+=g_cnt[i]; }
      off_s = o;
      if (p==0){
        int oo=0;
#pragma unroll
        for (int i=0;i<16;i++){ g_off[i]=oo; oo+=g_cnt[i]; }
        g_off[16]=oo;
      }
    }
    float r = g_rstd[t];
    float4 xv = ((const float4*)(x  + (size_t)t*DMODEL))[tid];
    float4 gv = ((const float4*)(g1 + (size_t)e*DMODEL))[tid];
    float v0=xv.x*gv.x*r, v1=xv.y*gv.y*r, v2=xv.z*gv.z*r, v3=xv.w*gv.w*r;
    float am = fmaxf(fmaxf(fabsf(v0),fabsf(v1)), fmaxf(fabsf(v2),fabsf(v3)));
    am = warpMax(am);
    int lane=tid&31, wid=tid>>5;
    if (lane==0) red[wid]=am;
    __syncthreads();
    if (tid==0){
      float m=0.f;
#pragma unroll
      for (int i=0;i<8;i++) m=fmaxf(m,red[i]);
      float as = 127.f/fmaxf(m,1e-5f);
      int slot = off_s + g_pair_pos[p];
      as_s = as; slot_s = slot;
      g_ascale1[slot]=as;
      g_slot_cw[slot]=g_pair_w[p];
      g_pair_slot[p]=slot;
    }
    __syncthreads();
    float as = as_s; int slot = slot_s;
    int q0 = max(-128, min(127, __float2int_rn(v0*as)));
    int q1 = max(-128, min(127, __float2int_rn(v1*as)));
    int q2 = max(-128, min(127, __float2int_rn(v2*as)));
    int q3 = max(-128, min(127, __float2int_rn(v3*as)));
    ((uint32_t*)(g_A1q + (size_t)slot*DMODEL))[tid] = pack4i8(q0,q1,q2,q3);
  } else {
    // ----- weight path: quantize to ternary int8 -----
    int b = blockIdx.x - NPAIR;      // 0..16383
    int m = b >> 9;
    int blk = b & 511;
    __shared__ float ws_s;
    if (tid==0) ws_s = wscale_from_parts(m);
    __syncthreads();
    float ws = ws_s;
    const float* src = ((m<16) ? (w1 + (size_t)m*ELEM_PER_MAT)
                               : (w2 + (size_t)(m-16)*ELEM_PER_MAT)) + (size_t)blk*8192;
    int8_t* dst = ((m<16) ? (g_W1q + (size_t)m*ELEM_PER_MAT)
                          : (g_W2q + (size_t)(m-16)*ELEM_PER_MAT)) + (size_t)blk*8192;
#pragma unroll
    for (int j=0;j<8;j++){
      float4 v = ((const float4*)src)[j*256 + tid];
      int q0 = max(-1, min(1, __float2int_rn(v.x*ws)));
      int q1 = max(-1, min(1, __float2int_rn(v.y*ws)));
      int q2 = max(-1, min(1, __float2int_rn(v.z*ws)));
      int q3 = max(-1, min(1, __float2int_rn(v.w*ws)));
      ((uint32_t*)dst)[j*256 + tid] = pack4i8(q0,q1,q2,q3);
    }
  }
}

// ---------------- int8 GEMM: mma.m16n8k32.s8, 128x128 tile, K=64/iter, 3-stage ---
// smem: 3 stages x (A 128x80 + B 128x80) = 61440 bytes (dynamic)
#define GEMM_SMEM 61440
template<int KDIM, int NTOT, bool L1>
__global__ void __launch_bounds__(256) gemm_i8(float* __restrict__ outp)
{
  extern __shared__ int8_t smdyn[];
  const int e  = blockIdx.z;
  const int mt = blockIdx.x;
  const int nt = blockIdx.y;
  const int cnt = g_cnt[e];
  if (mt*128 >= cnt) return;
  const int off = g_off[e];
  const int8_t* __restrict__ A = (L1 ? g_A1q : g_A2q) + (size_t)off*KDIM;
  const int8_t* __restrict__ W = (L1 ? g_W1q : g_W2q)
                                 + ((size_t)e*NTOT + (size_t)nt*128)*(size_t)KDIM;
  const uint32_t sb = smem_u32(smdyn);
  const int tid = threadIdx.x;
  const int lane = tid & 31, warp = tid >> 5;
  const int wm = warp >> 2, wn = warp & 3;   // 2x4 warp grid, warp tile 64x32
  const int gq = lane >> 2, tq = lane & 3;

  __shared__ float ws_s;
  if (tid==0) ws_s = wscale_from_parts(L1 ? e : 16+e);

  // loader: 2 chunks of 16B per matrix per thread per stage (128 rows x 64B)
  uint32_t sof[2]; const int8_t* asrc[2]; const int8_t* bsrc[2]; uint32_t apred[2];
#pragma unroll
  for (int p=0;p<2;p++){
    int c = p*256 + tid;
    int row = c>>2, seg = (c&3)*16;
    sof[p] = (uint32_t)(row*80 + seg);
    int gr = mt*128 + row;
    apred[p] = (gr < cnt) ? 16u : 0u;
    int grc = gr < cnt ? gr : cnt-1;
    asrc[p] = A + (size_t)grc*KDIM + seg;
    bsrc[p] = W + (size_t)row*KDIM + seg;   // row only: W already carries nt*128
  }

  auto load_stage = [&](int st, int kt){
    uint32_t ab = sb + (uint32_t)st*20480;
    uint32_t bb = ab + 10240;
    size_t ko = (size_t)kt*64;
#pragma unroll
    for (int p=0;p<2;p++){
      asm volatile("cp.async.cg.shared.global [%0],[%1],16,%2;"
                   :: "r"(ab+sof[p]), "l"(asrc[p]+ko), "r"(apred[p]));
      asm volatile("cp.async.cg.shared.global [%0],[%1],16;"
                   :: "r"(bb+sof[p]), "l"(bsrc[p]+ko));
    }
    asm volatile("cp.async.commit_group;");
  };

  int acc[4][4][4];
#pragma unroll
  for (int a=0;a<4;a++)
#pragma unroll
    for (int b=0;b<4;b++)
#pragma unroll
      for (int c=0;c<4;c++) acc[a][b][c]=0;

  load_stage(0,0);
  load_stage(1,1);

  constexpr int KT = KDIM/64;
  for (int kt=0; kt<KT; kt++){
    const int st = kt%3;
    asm volatile("cp.async.wait_group 1;");
    __syncthreads();
    if (kt+2 < KT) load_stage((kt+2)%3, kt+2);
    else asm volatile("cp.async.commit_group;");

    uint32_t abase = sb + (uint32_t)st*20480;
    uint32_t bbase = abase + 10240;
#pragma unroll
    for (int h=0;h<2;h++){
      uint32_t af[4][4], bf[4][2];
#pragma unroll
      for (int mi=0;mi<4;mi++){
        uint32_t addr = abase + (uint32_t)((wm*64 + mi*16 + (lane&15))*80 + h*32 + ((lane>>4)*16));
        asm volatile("ldmatrix.sync.aligned.m8n8.x4.shared.b16 {%0,%1,%2,%3},[%4];"
                     : "=r"(af[mi][0]),"=r"(af[mi][1]),"=r"(af[mi][2]),"=r"(af[mi][3])
                     : "r"(addr));
      }
#pragma unroll
      for (int ni=0;ni<4;ni++){
        uint32_t addr = bbase + (uint32_t)((wn*32 + ni*8 + (lane&7))*80 + h*32 + (((lane>>3)&1)*16));
        asm volatile("ldmatrix.sync.aligned.m8n8.x2.shared.b16 {%0,%1},[%2];"
                     : "=r"(bf[ni][0]),"=r"(bf[ni][1])
                     : "r"(addr));
      }
#pragma unroll
      for (int mi=0;mi<4;mi++)
#pragma unroll
        for (int ni=0;ni<4;ni++)
          asm volatile(
            "mma.sync.aligned.m16n8k32.row.col.s32.s8.s8.s32 "
            "{%0,%1,%2,%3}, {%4,%5,%6,%7}, {%8,%9}, {%0,%1,%2,%3};"
            : "+r"(acc[mi][ni][0]), "+r"(acc[mi][ni][1]),
              "+r"(acc[mi][ni][2]), "+r"(acc[mi][ni][3])
            : "r"(af[mi][0]), "r"(af[mi][1]), "r"(af[mi][2]), "r"(af[mi][3]),
              "r"(bf[ni][0]), "r"(bf[ni][1]));
    }
  }

  // ---------------- epilogue ----------------
  const int base_m = mt*128 + wm*64;
  const int base_n = nt*128 + wn*32;
  const float ws = ws_s;
#pragma unroll
  for (int mi=0;mi<4;mi++){
#pragma unroll
    for (int h=0;h<2;h++){
      int r = base_m + mi*16 + gq + h*8;
      if (r < cnt){
        int slot = off + r;
        if (L1){
          float dq = 1.f/(g_ascale1[slot]*ws);
          float* Hr = g_H + (size_t)slot*DFF;
#pragma unroll
          for (int ni=0;ni<4;ni++){
            int c = base_n + ni*8 + tq*2;
            float2 v;
            v.x = gelu_tanh((float)acc[mi][ni][h*2+0]*dq);
            v.y = gelu_tanh((float)acc[mi][ni][h*2+1]*dq);
            *(float2*)&Hr[c] = v;
          }
        } else {
          float coef = g_slot_cw[slot]/(g_ascale2[slot]*ws);
          float* Or = g_H + (size_t)slot*DMODEL;   // reuse g_H as per-slot O rows
#pragma unroll
          for (int ni=0;ni<4;ni++){
            int c = base_n + ni*8 + tq*2;
            float2 v;
            v.x = (float)acc[mi][ni][h*2+0]*coef;
            v.y = (float)acc[mi][ni][h*2+1]*coef;
            *(float2*)&Or[c] = v;
          }
        }
      }
    }
  }
}

// ---------------- k_aux: per-expert probs sums ----------------
__global__ void k_aux(){
  int e = blockIdx.x;
  int tid = threadIdx.x;  // 256
  const float* pr = g_probs + (size_t)e*NTOK;
  float s = 0.f;
  for (int i=tid;i<NTOK;i+=256) s += pr[i];
  s = warpSum(s);
  __shared__ float sm[8];
  int lane=tid&31, wid=tid>>5;
  if (lane==0) sm[wid]=s;
  __syncthreads();
  if (tid==0){
    float tot=0.f;
#pragma unroll
    for (int i=0;i<8;i++) tot+=sm[i];
    g_paux[e]=tot;
  }
}

// ---------------- k6: layer-2 rmsnorm + act_quant to int8 ----------------
__global__ void k6_quant2(const float* __restrict__ g2){
  int slot = blockIdx.x;
  int e = 0;
#pragma unroll
  for (int i=1;i<NEXP;i++) if (slot >= g_off[i]) e = i;
  const float4* h4 = (const float4*)(g_H + (size_t)slot*DFF);
  const float4* g4 = (const float4*)(g2  + (size_t)e*DFF);
  int tid = threadIdx.x;  // 256
  float v[16]; float ss=0.f;
#pragma unroll
  for (int j=0;j<4;j++){
    float4 a = h4[tid*4+j];
    v[j*4+0]=a.x; v[j*4+1]=a.y; v[j*4+2]=a.z; v[j*4+3]=a.w;
    ss += a.x*a.x + a.y*a.y + a.z*a.z + a.w*a.w;
  }
  ss = warpSum(ss);
  __shared__ float sred[8];
  __shared__ float rstd_s, as_s;
  int lane=tid&31, wid=tid>>5;
  if (lane==0) sred[wid]=ss;
  __syncthreads();
  if (tid==0){
    float s=0.f;
#pragma unroll
    for (int i=0;i<8;i++) s+=sred[i];
    rstd_s = rsqrtf(s*(1.f/DFF) + 1e-6f);
  }
  __syncthreads();
  float r2 = rstd_s;
  float am = 0.f;
#pragma unroll
  for (int j=0;j<4;j++){
    float4 gg = g4[tid*4+j];
    v[j*4+0]*=gg.x*r2; v[j*4+1]*=gg.y*r2; v[j*4+2]*=gg.z*r2; v[j*4+3]*=gg.w*r2;
#pragma unroll
    for (int k=0;k<4;k++) am = fmaxf(am, fabsf(v[j*4+k]));
  }
  am = warpMax(am);
  if (lane==0) sred[wid]=am;
  __syncthreads();
  if (tid==0){
    float m=0.f;
#pragma unroll
    for (int i=0;i<8;i++) m=fmaxf(m,sred[i]);
    as_s = 127.f/fmaxf(m,1e-5f);
    g_ascale2[slot]=as_s;
  }
  __syncthreads();
  float as = as_s;
  uint32_t o[4];
#pragma unroll
  for (int j=0;j<4;j++){
    int q0 = max(-128, min(127, __float2int_rn(v[j*4+0]*as)));
    int q1 = max(-128, min(127, __float2int_rn(v[j*4+1]*as)));
    int q2 = max(-128, min(127, __float2int_rn(v[j*4+2]*as)));
    int q3 = max(-128, min(127, __float2int_rn(v[j*4+3]*as)));
    o[j] = pack4i8(q0,q1,q2,q3);
  }
  uint4 ov; ov.x=o[0]; ov.y=o[1]; ov.z=o[2]; ov.w=o[3];
  ((uint4*)(g_A2q + (size_t)slot*DFF))[tid] = ov;
}

// ---------------- k7: combine rows, write aux, reset counters (block 0 only, ordered) ----
__global__ void k7_combine(float* __restrict__ out, long long out_size){
  int t = blockIdx.x;
  int tid = threadIdx.x;  // 256
  int s0 = g_pair_slot[2*t];
  int s1 = g_pair_slot[2*t+1];
  const float4* a = (const float4*)(g_H + (size_t)s0*DMODEL);
  const float4* b = (const float4*)(g_H + (size_t)s1*DMODEL);
  float4 va = a[tid], vb = b[tid];
  float4 r; r.x=va.x+vb.x; r.y=va.y+vb.y; r.z=va.z+vb.z; r.w=va.w+vb.w;
  ((float4*)(out + (size_t)t*DMODEL))[tid] = r;
  if (blockIdx.x==0){
    // aux loss first (reads g_fcnt), THEN reset counters — ordered by __syncthreads
    if (tid==0 && out_size > (long long)NTOK*DMODEL){
      float aux=0.f;
#pragma unroll
      for (int e=0;e<16;e++)
        aux += ((float)g_fcnt[e]/(float)(NTOK*2)) * (g_paux[e]*(1.f/NTOK));
      out[(size_t)NTOK*DMODEL] = (float)NEXP * aux;
    }
    __syncthreads();
    if (tid<16){ g_cnt[tid]=0; g_fcnt[tid]=0; }
  }
}

// ---------------- launch ----------------
extern "C" void kernel_launch(void* const* d_in, const int* in_sizes, int n_in,
                              void* d_out, int out_size){
  const float* x  = (const float*)d_in[0];
  const float* rw = (const float*)d_in[1];
  const float* w1 = (const float*)d_in[2];
  const float* g1 = (const float*)d_in[3];
  const float* w2 = (const float*)d_in[4];
  const float* g2 = (const float*)d_in[5];
  float* out = (float*)d_out;

  cudaFuncSetAttribute((const void*)gemm_i8<DMODEL,DFF,true>,
                       cudaFuncAttributeMaxDynamicSharedMemorySize, GEMM_SMEM);
  cudaFuncSetAttribute((const void*)gemm_i8<DFF,DMODEL,false>,
                       cudaFuncAttributeMaxDynamicSharedMemorySize, GEMM_SMEM);

  kA_wsum<<<dim3(64,32),256>>>(w1, w2);
  k2_router<<<NTOK,128>>>(x, rw);
  k45<<<NPAIR+16384,256>>>(x, g1, w1, w2);
  gemm_i8<DMODEL,DFF,true><<<dim3(64,DFF/128,NEXP),256,GEMM_SMEM>>>(nullptr);
  k_aux<<<NEXP,256>>>();
  k6_quant2<<<NPAIR,256>>>(g2);
  gemm_i8<DFF,DMODEL,false><<<dim3(64,DMODEL/128,NEXP),256,GEMM_SMEM>>>(out);
  k7_combine<<<NTOK,256>>>(out, (long long)out_size);
}